// round 2
// baseline (speedup 1.0000x reference)
#include <cuda_runtime.h>

#define NN 8192
#define VV 8
#define OO 16
#define HH 128
#define ROW (4*VV + 3*OO)   // 80 floats per input row

// Global scratch accumulators (no allocations allowed)
__device__ double g_dist;
__device__ double g_oinv;
__device__ double g_vinv;
__device__ unsigned long long g_ocnt;
__device__ unsigned long long g_vcnt;

__global__ void zero_kernel() {
    g_dist = 0.0;
    g_oinv = 0.0;
    g_vinv = 0.0;
    g_ocnt = 0ull;
    g_vcnt = 0ull;
}

__inline__ __device__ float warp_red_f(float v) {
    #pragma unroll
    for (int o = 16; o > 0; o >>= 1) v += __shfl_down_sync(0xffffffffu, v, o);
    return v;
}
__inline__ __device__ int warp_red_i(int v) {
    #pragma unroll
    for (int o = 16; o > 0; o >>= 1) v += __shfl_down_sync(0xffffffffu, v, o);
    return v;
}

// One thread per (n, v). 8 vehicles of one n sit in 8 adjacent lanes so
// vehicle-vehicle distances come from __shfl_down_sync.
__global__ void __launch_bounds__(256) loss_kernel(
    const float* __restrict__ pred,     // (N, V, H) f32
    const float* __restrict__ inputs)   // (N, 80) f32
{
    const int gid = blockIdx.x * blockDim.x + threadIdx.x;   // 0..N*V-1
    const int n = gid >> 3;
    const int v = gid & 7;

    const float* row = inputs + (size_t)n * ROW;

    float x  = row[4*v + 0];
    float y  = row[4*v + 1];
    const float tx = row[4*v + 2];
    const float ty = row[4*v + 3];

    // Obstacles: precompute squared effective radius; r<=0 => never masked.
    float ox[OO], oy[OO], r2[OO];
    #pragma unroll
    for (int o = 0; o < OO; ++o) {
        ox[o] = row[4*VV + 3*o + 0];
        oy[o] = row[4*VV + 3*o + 1];
        float r = row[4*VV + 3*o + 2] + 1.0f;   // + OBST_RADIUS
        r2[o] = (r > 0.0f) ? r * r : -1.0f;
    }

    const float4* p4 = (const float4*)(pred + (size_t)gid * HH);

    float dist_sum = 0.0f;
    float oinv = 0.0f, vinv = 0.0f;
    int ocnt = 0, vcnt = 0;
    const bool vact = (v < 7);

    #pragma unroll 1
    for (int hb = 0; hb < HH / 4; ++hb) {
        float4 p = p4[hb];
        float pv[4] = {p.x, p.y, p.z, p.w};
        #pragma unroll
        for (int j = 0; j < 4; ++j) {
            float s, c;
            __sincosf(pv[j], &s, &c);
            x += 2.0f * c;           // STEP = 2
            y += 2.0f * s;

            // target-distance term
            float dx = tx - x, dy = ty - y;
            dist_sum += sqrtf(fmaf(dx, dx, dy * dy));

            // obstacle term: d2 < r2  <=>  od < r (r>0)
            #pragma unroll
            for (int o = 0; o < OO; ++o) {
                float ax = x - ox[o], ay = y - oy[o];
                float d2 = fmaf(ax, ax, ay * ay);
                if (d2 < r2[o]) { oinv += rsqrtf(d2); ocnt++; }
            }

            // vehicle-vehicle term: neighbor (v+1) is the next lane
            float xn = __shfl_down_sync(0xffffffffu, x, 1);
            float yn = __shfl_down_sync(0xffffffffu, y, 1);
            if (vact) {
                float bx = xn - x, by = yn - y;
                float d2 = fmaf(bx, bx, by * by);
                if (d2 < 1.0f) { vinv += rsqrtf(d2); vcnt++; }   // VEH_RADIUS^2 = 1
            }
        }
    }

    // ---- reduction: warp -> block -> global atomics ----
    dist_sum = warp_red_f(dist_sum);
    oinv     = warp_red_f(oinv);
    vinv     = warp_red_f(vinv);
    ocnt     = warp_red_i(ocnt);
    vcnt     = warp_red_i(vcnt);

    __shared__ float sd[8], so[8], sv[8];
    __shared__ int soc[8], svc[8];
    const int wid = threadIdx.x >> 5;
    const int lane = threadIdx.x & 31;
    if (lane == 0) {
        sd[wid] = dist_sum; so[wid] = oinv; sv[wid] = vinv;
        soc[wid] = ocnt; svc[wid] = vcnt;
    }
    __syncthreads();
    if (wid == 0) {
        float d = (lane < 8) ? sd[lane] : 0.0f;
        float a = (lane < 8) ? so[lane] : 0.0f;
        float b = (lane < 8) ? sv[lane] : 0.0f;
        int   c = (lane < 8) ? soc[lane] : 0;
        int   e = (lane < 8) ? svc[lane] : 0;
        d = warp_red_f(d); a = warp_red_f(a); b = warp_red_f(b);
        c = warp_red_i(c); e = warp_red_i(e);
        if (lane == 0) {
            atomicAdd(&g_dist, (double)d);
            atomicAdd(&g_oinv, (double)a);
            atomicAdd(&g_vinv, (double)b);
            atomicAdd(&g_ocnt, (unsigned long long)c);
            atomicAdd(&g_vcnt, (unsigned long long)e);
        }
    }
}

__global__ void finalize_kernel(float* __restrict__ out) {
    double loss = g_dist / ((double)NN * VV * HH);            // DIST_COST = 1
    if (g_ocnt > 0) loss += (g_oinv / (double)g_ocnt) * 0.1;  // OBST_COST
    if (g_vcnt > 0) loss += (g_vinv / (double)g_vcnt) * 0.1;  // VEH_COST
    out[0] = (float)loss;
}

extern "C" void kernel_launch(void* const* d_in, const int* in_sizes, int n_in,
                              void* d_out, int out_size) {
    const float* pred   = (const float*)d_in[0];   // (N, V, H, 1) f32
    const float* inputs = (const float*)d_in[1];   // (N, 80) f32
    float* out = (float*)d_out;

    zero_kernel<<<1, 1>>>();
    loss_kernel<<<(NN * VV) / 256, 256>>>(pred, inputs);
    finalize_kernel<<<1, 1>>>(out);
}

// round 3
// speedup vs baseline: 2.4782x; 2.4782x over previous
#include <cuda_runtime.h>

#define NN 8192
#define VV 8
#define OO 16
#define HH 128
#define ROW (4*VV + 3*OO)   // 80 floats per input row
#define NBLK 256            // (NN*VV)/256

// Per-block partials (plain stores; no zeroing kernel, no atomics)
__device__ float g_pd[NBLK];   // dist sums
__device__ float g_po[NBLK];   // obstacle 1/d sums
__device__ float g_pv[NBLK];   // vehicle  1/d sums
__device__ int   g_oc[NBLK];   // obstacle mask counts
__device__ int   g_vc[NBLK];   // vehicle  mask counts

__inline__ __device__ float warp_red_f(float v) {
    #pragma unroll
    for (int o = 16; o > 0; o >>= 1) v += __shfl_down_sync(0xffffffffu, v, o);
    return v;
}
__inline__ __device__ int warp_red_i(int v) {
    #pragma unroll
    for (int o = 16; o > 0; o >>= 1) v += __shfl_down_sync(0xffffffffu, v, o);
    return v;
}

// One thread per (n, v). 8 vehicles of one n sit in 8 adjacent lanes so
// vehicle-vehicle distances come from __shfl_down_sync.
__global__ void __launch_bounds__(256) loss_kernel(
    const float* __restrict__ pred,     // (N, V, H) f32
    const float* __restrict__ inputs)   // (N, 80) f32
{
    const int gid = blockIdx.x * blockDim.x + threadIdx.x;   // 0..N*V-1
    const int n = gid >> 3;
    const int v = gid & 7;

    const float* row = inputs + (size_t)n * ROW;

    float x  = row[4*v + 0];
    float y  = row[4*v + 1];
    const float tx = row[4*v + 2];
    const float ty = row[4*v + 3];

    // Obstacles: squared effective radius; r<=0 => never masked.
    // Also build an exact prune box: if the point is farther than rmax outside
    // the center bbox along either axis, then for EVERY obstacle d > r_o
    // (d >= axis separation > rmax >= r_o), so no mask can fire.
    float ox[OO], oy[OO], r2[OO];
    float minx = 1e30f, maxx = -1e30f, miny = 1e30f, maxy = -1e30f, rmax = -1e30f;
    #pragma unroll
    for (int o = 0; o < OO; ++o) {
        float cx = row[4*VV + 3*o + 0];
        float cy = row[4*VV + 3*o + 1];
        float r  = row[4*VV + 3*o + 2] + 1.0f;   // + OBST_RADIUS
        ox[o] = cx; oy[o] = cy;
        r2[o] = (r > 0.0f) ? r * r : -1.0f;
        minx = fminf(minx, cx); maxx = fmaxf(maxx, cx);
        miny = fminf(miny, cy); maxy = fmaxf(maxy, cy);
        rmax = fmaxf(rmax, r);
    }
    const float bx0 = minx - rmax, bx1 = maxx + rmax;
    const float by0 = miny - rmax, by1 = maxy + rmax;

    const float4* p4 = (const float4*)(pred + (size_t)gid * HH);

    float dist_sum = 0.0f;
    float oinv = 0.0f, vinv = 0.0f;
    int ocnt = 0, vcnt = 0;
    const bool vact = (v < 7);

    #pragma unroll 1
    for (int hb = 0; hb < HH / 4; ++hb) {
        float4 p = p4[hb];
        float pv[4] = {p.x, p.y, p.z, p.w};
        #pragma unroll
        for (int j = 0; j < 4; ++j) {
            float s, c;
            __sincosf(pv[j], &s, &c);
            x += 2.0f * c;           // STEP = 2
            y += 2.0f * s;

            // target-distance term (always)
            float dx = tx - x, dy = ty - y;
            dist_sum += sqrtf(fmaf(dx, dx, dy * dy));

            // obstacle term, pruned: only enter when a mask hit is possible
            if (x >= bx0 && x <= bx1 && y >= by0 && y <= by1) {
                #pragma unroll
                for (int o = 0; o < OO; ++o) {
                    float ax = x - ox[o], ay = y - oy[o];
                    float d2 = fmaf(ax, ax, ay * ay);
                    if (d2 < r2[o]) { oinv += rsqrtf(d2); ocnt++; }
                }
            }

            // vehicle-vehicle term: neighbor (v+1) is the next lane
            float xn = __shfl_down_sync(0xffffffffu, x, 1);
            float yn = __shfl_down_sync(0xffffffffu, y, 1);
            if (vact) {
                float bxv = xn - x, byv = yn - y;
                float d2 = fmaf(bxv, bxv, byv * byv);
                if (d2 < 1.0f) { vinv += rsqrtf(d2); vcnt++; }   // VEH_RADIUS^2 = 1
            }
        }
    }

    // ---- reduction: warp -> block -> per-block partial stores ----
    dist_sum = warp_red_f(dist_sum);
    oinv     = warp_red_f(oinv);
    vinv     = warp_red_f(vinv);
    ocnt     = warp_red_i(ocnt);
    vcnt     = warp_red_i(vcnt);

    __shared__ float sd[8], so[8], sv[8];
    __shared__ int soc[8], svc[8];
    const int wid = threadIdx.x >> 5;
    const int lane = threadIdx.x & 31;
    if (lane == 0) {
        sd[wid] = dist_sum; so[wid] = oinv; sv[wid] = vinv;
        soc[wid] = ocnt; svc[wid] = vcnt;
    }
    __syncthreads();
    if (wid == 0) {
        float d = (lane < 8) ? sd[lane] : 0.0f;
        float a = (lane < 8) ? so[lane] : 0.0f;
        float b = (lane < 8) ? sv[lane] : 0.0f;
        int   cc = (lane < 8) ? soc[lane] : 0;
        int   e = (lane < 8) ? svc[lane] : 0;
        d = warp_red_f(d); a = warp_red_f(a); b = warp_red_f(b);
        cc = warp_red_i(cc); e = warp_red_i(e);
        if (lane == 0) {
            g_pd[blockIdx.x] = d;
            g_po[blockIdx.x] = a;
            g_pv[blockIdx.x] = b;
            g_oc[blockIdx.x] = cc;
            g_vc[blockIdx.x] = e;
        }
    }
}

__global__ void __launch_bounds__(NBLK) finalize_kernel(float* __restrict__ out) {
    const int t = threadIdx.x;
    float d = g_pd[t], a = g_po[t], b = g_pv[t];
    int   c = g_oc[t], e = g_vc[t];

    d = warp_red_f(d); a = warp_red_f(a); b = warp_red_f(b);
    c = warp_red_i(c); e = warp_red_i(e);

    __shared__ float sd[8], so[8], sv[8];
    __shared__ int soc[8], svc[8];
    const int wid = t >> 5, lane = t & 31;
    if (lane == 0) { sd[wid] = d; so[wid] = a; sv[wid] = b; soc[wid] = c; svc[wid] = e; }
    __syncthreads();
    if (wid == 0) {
        d = (lane < 8) ? sd[lane] : 0.0f;
        a = (lane < 8) ? so[lane] : 0.0f;
        b = (lane < 8) ? sv[lane] : 0.0f;
        c = (lane < 8) ? soc[lane] : 0;
        e = (lane < 8) ? svc[lane] : 0;
        d = warp_red_f(d); a = warp_red_f(a); b = warp_red_f(b);
        c = warp_red_i(c); e = warp_red_i(e);
        if (lane == 0) {
            double loss = (double)d / ((double)NN * VV * HH);      // DIST_COST = 1
            if (c > 0) loss += ((double)a / (double)c) * 0.1;      // OBST_COST
            if (e > 0) loss += ((double)b / (double)e) * 0.1;      // VEH_COST
            out[0] = (float)loss;
        }
    }
}

extern "C" void kernel_launch(void* const* d_in, const int* in_sizes, int n_in,
                              void* d_out, int out_size) {
    const float* pred   = (const float*)d_in[0];   // (N, V, H, 1) f32
    const float* inputs = (const float*)d_in[1];   // (N, 80) f32
    float* out = (float*)d_out;

    loss_kernel<<<NBLK, 256>>>(pred, inputs);
    finalize_kernel<<<1, NBLK>>>(out);
}